// round 1
// baseline (speedup 1.0000x reference)
#include <cuda_runtime.h>
#include <cstdint>
#include <cstddef>

#define N_NODES 8192
#define DHID 64

// ---------------- scratch (device globals; no allocation allowed) ----------------
__device__ __align__(16) float g_Hcl[N_NODES * DHID];
__device__ __align__(16) float g_Hue[N_NODES * DHID];
__device__ __align__(16) float g_Xc1[N_NODES * DHID];
__device__ __align__(16) float g_Xc2[N_NODES * DHID];
__device__ __align__(16) float g_Xue[N_NODES * DHID];
__device__ __align__(16) float g_part[512 * DHID];

__device__ __forceinline__ float relu_(float x) { return fmaxf(x, 0.0f); }

__device__ __forceinline__ unsigned f2tf32(float x) {
    unsigned u;
    asm("cvt.rna.tf32.f32 %0, %1;" : "=r"(u) : "f"(x));
    return u;
}

__device__ __forceinline__ void mma_tf32(float* c, const unsigned* a, const unsigned* b) {
    asm volatile(
        "mma.sync.aligned.m16n8k8.row.col.f32.tf32.tf32.f32 "
        "{%0,%1,%2,%3}, {%4,%5,%6,%7}, {%8,%9}, {%0,%1,%2,%3};\n"
        : "+f"(c[0]), "+f"(c[1]), "+f"(c[2]), "+f"(c[3])
        : "r"(a[0]), "r"(a[1]), "r"(a[2]), "r"(a[3]), "r"(b[0]), "r"(b[1]));
}

// ---------------- big GEMM: C = A @ H  (M=8192, K=8192, Nd = 64*NT) ----------------
// NT=1: C0(g_Xc1) = A_cl @ g_Hcl
// NT=2: [C0|C1] = A_ue @ [g_Hue | g_Hcl]  -> C0 = g_Xc2, C1 = g_Xue
template <int NT>
__global__ void __launch_bounds__(256, 2) gemm_kernel(const float* __restrict__ A) {
    constexpr int ND   = 64 * NT;
    constexpr int KC   = 32;
    constexpr int ASTR = 36;        // A smem row stride (floats) -> conflict-free frag loads
    constexpr int BSTR = ND + 8;    // B smem row stride          -> conflict-free frag loads
    constexpr int ASZ  = 64 * ASTR;
    constexpr int BSZ  = KC * BSTR;
    constexpr int WN   = ND / 4;    // warp n-width (warps tiled 2(M) x 4(N))
    constexpr int NTT  = WN / 8;    // n-tiles of 8 per warp
    constexpr int NBJ  = 2 * NT;    // float4 B loads per thread per chunk

    extern __shared__ float smem[];
    float* As = smem;             // [2][ASZ]
    float* Bs = smem + 2 * ASZ;   // [2][BSZ]

    const float* B0;
    const float* B1;
    float* C0;
    float* C1;
    if (NT == 1) { B0 = g_Hcl; B1 = nullptr; C0 = g_Xc1; C1 = nullptr; }
    else         { B0 = g_Hue; B1 = g_Hcl;   C0 = g_Xc2; C1 = g_Xue;  }

    const int tid    = threadIdx.x;
    const int lane   = tid & 31;
    const int wid    = tid >> 5;
    const int warp_m = wid & 1;   // 0..1
    const int warp_n = wid >> 1;  // 0..3
    const int m0     = blockIdx.x * 64;

    // ---- global load coords (per chunk) ----
    const int ar = tid >> 3;          // A row 0..31 (and +32)
    const int ac = (tid & 7) * 4;     // A col-in-chunk
    const float* gA0 = A + (size_t)(m0 + ar) * N_NODES + ac;
    const float* gA1 = A + (size_t)(m0 + ar + 32) * N_NODES + ac;

    const float* gB[NBJ];
    int bso[NBJ];
    #pragma unroll
    for (int j = 0; j < NBJ; ++j) {
        int idx  = tid + j * 256;
        int row  = idx / (16 * NT);        // 0..31 (k within chunk)
        int colf = (idx % (16 * NT)) * 4;  // 0..ND-4
        bso[j] = row * BSTR + colf;
        if (NT == 2 && colf >= 64) gB[j] = B1 + (size_t)row * 64 + (colf - 64);
        else                       gB[j] = B0 + (size_t)row * 64 + colf;
    }

    float4 ra0, ra1, rb[NBJ];

    auto GLOAD = [&](int kt) {
        const size_t ko = (size_t)kt * KC;
        ra0 = *(const float4*)(gA0 + ko);
        ra1 = *(const float4*)(gA1 + ko);
        #pragma unroll
        for (int j = 0; j < NBJ; ++j)
            rb[j] = *(const float4*)(gB[j] + ko * 64);
    };
    auto SSTORE = [&](int buf) {
        float* ap = As + buf * ASZ;
        float4 t;
        t.x = __uint_as_float(f2tf32(ra0.x)); t.y = __uint_as_float(f2tf32(ra0.y));
        t.z = __uint_as_float(f2tf32(ra0.z)); t.w = __uint_as_float(f2tf32(ra0.w));
        *(float4*)(ap + ar * ASTR + ac) = t;
        t.x = __uint_as_float(f2tf32(ra1.x)); t.y = __uint_as_float(f2tf32(ra1.y));
        t.z = __uint_as_float(f2tf32(ra1.z)); t.w = __uint_as_float(f2tf32(ra1.w));
        *(float4*)(ap + (ar + 32) * ASTR + ac) = t;
        float* bp = Bs + buf * BSZ;
        #pragma unroll
        for (int j = 0; j < NBJ; ++j) {
            float4 u;
            u.x = __uint_as_float(f2tf32(rb[j].x)); u.y = __uint_as_float(f2tf32(rb[j].y));
            u.z = __uint_as_float(f2tf32(rb[j].z)); u.w = __uint_as_float(f2tf32(rb[j].w));
            *(float4*)(bp + bso[j]) = u;
        }
    };

    float acc[2][NTT][4];
    #pragma unroll
    for (int mt = 0; mt < 2; ++mt)
        #pragma unroll
        for (int nt = 0; nt < NTT; ++nt)
            #pragma unroll
            for (int i = 0; i < 4; ++i) acc[mt][nt][i] = 0.0f;

    GLOAD(0);
    SSTORE(0);
    __syncthreads();

    const int NKT = N_NODES / KC;  // 256
    const int mlo = lane >> 2;
    const int klo = lane & 3;

    for (int kt = 0; kt < NKT; ++kt) {
        const int buf = kt & 1;
        if (kt + 1 < NKT) GLOAD(kt + 1);

        const float* ap = As + buf * ASZ + (warp_m * 32 + mlo) * ASTR + klo;
        const float* bp = Bs + buf * BSZ + klo * BSTR + warp_n * WN + mlo;

        #pragma unroll
        for (int kk = 0; kk < 4; ++kk) {
            unsigned af[2][4], bf[NTT][2];
            #pragma unroll
            for (int mt = 0; mt < 2; ++mt) {
                const float* p = ap + mt * 16 * ASTR + kk * 8;
                af[mt][0] = __float_as_uint(p[0]);
                af[mt][1] = __float_as_uint(p[8 * ASTR]);
                af[mt][2] = __float_as_uint(p[4]);
                af[mt][3] = __float_as_uint(p[8 * ASTR + 4]);
            }
            #pragma unroll
            for (int nt = 0; nt < NTT; ++nt) {
                const float* p = bp + kk * 8 * BSTR + nt * 8;
                bf[nt][0] = __float_as_uint(p[0]);
                bf[nt][1] = __float_as_uint(p[4 * BSTR]);
            }
            #pragma unroll
            for (int mt = 0; mt < 2; ++mt)
                #pragma unroll
                for (int nt = 0; nt < NTT; ++nt)
                    mma_tf32(acc[mt][nt], af[mt], bf[nt]);
        }

        if (kt + 1 < NKT) SSTORE(buf ^ 1);
        __syncthreads();
    }

    // ---- epilogue ----
    const int c2 = (lane & 3) * 2;
    #pragma unroll
    for (int mt = 0; mt < 2; ++mt) {
        int r = m0 + warp_m * 32 + mt * 16 + mlo;
        #pragma unroll
        for (int nt = 0; nt < NTT; ++nt) {
            int n = warp_n * WN + nt * 8 + c2;
            float* Cg = C0;
            int nn = n;
            if (NT == 2 && n >= 64) { Cg = C1; nn = n - 64; }
            *(float2*)(Cg + (size_t)r * 64 + nn)       = make_float2(acc[mt][nt][0], acc[mt][nt][1]);
            *(float2*)(Cg + (size_t)(r + 8) * 64 + nn) = make_float2(acc[mt][nt][2], acc[mt][nt][3]);
        }
    }
}

// ---------------- layer 0 H (in_dim = 2) ----------------
__global__ void h_layer0_kernel(const float* __restrict__ X1, const float* __restrict__ X2,
                                const float* __restrict__ XU,
                                const float* __restrict__ w1, const float* __restrict__ b1,
                                const float* __restrict__ w2, const float* __restrict__ b2,
                                const float* __restrict__ w3, const float* __restrict__ b3) {
    int t = blockIdx.x * 256 + threadIdx.x;  // over 8192*64
    int r = t >> 6, c = t & 63;
    float x10 = X1[r * 2], x11 = X1[r * 2 + 1];
    float x20 = X2[r * 2], x21 = X2[r * 2 + 1];
    float xu0 = XU[r * 2], xu1 = XU[r * 2 + 1];
    float h1 = relu_(fmaf(x10, w1[c], fmaf(x11, w1[64 + c], b1[c])));
    float h2 = relu_(fmaf(x20, w2[c], fmaf(x21, w2[64 + c], b2[c])));
    g_Hcl[t] = h1 + h2;
    g_Hue[t] = relu_(fmaf(xu0, w3[c], fmaf(xu1, w3[64 + c], b3[c])));
}

// ---------------- layers 1..2 H (in_dim = 64) ----------------
__global__ void __launch_bounds__(256) h_layer_kernel(const float* __restrict__ w1,
                                                      const float* __restrict__ b1,
                                                      const float* __restrict__ w2,
                                                      const float* __restrict__ b2,
                                                      const float* __restrict__ w3,
                                                      const float* __restrict__ b3) {
    __shared__ float xs1[16][64], xs2[16][64], xs3[16][64];
    const int tid = threadIdx.x;
    const int r0  = blockIdx.x * 16;
    #pragma unroll
    for (int i = 0; i < 4; ++i) {
        int idx = tid + i * 256;
        int r = idx >> 6, k = idx & 63;
        xs1[r][k] = g_Xc1[(size_t)(r0 + r) * 64 + k];
        xs2[r][k] = g_Xc2[(size_t)(r0 + r) * 64 + k];
        xs3[r][k] = g_Xue[(size_t)(r0 + r) * 64 + k];
    }
    __syncthreads();
    const int c  = tid & 63;
    const int rg = tid >> 6;  // 0..3, handles rows rg + 4*i
    float a1[4] = {0, 0, 0, 0}, a2[4] = {0, 0, 0, 0}, a3[4] = {0, 0, 0, 0};
    #pragma unroll 8
    for (int k = 0; k < 64; ++k) {
        float w1k = w1[k * 64 + c], w2k = w2[k * 64 + c], w3k = w3[k * 64 + c];
        #pragma unroll
        for (int i = 0; i < 4; ++i) {
            int r = rg + i * 4;
            a1[i] = fmaf(xs1[r][k], w1k, a1[i]);
            a2[i] = fmaf(xs2[r][k], w2k, a2[i]);
            a3[i] = fmaf(xs3[r][k], w3k, a3[i]);
        }
    }
    float bb1 = b1[c], bb2 = b2[c], bb3 = b3[c];
    #pragma unroll
    for (int i = 0; i < 4; ++i) {
        int r = rg + i * 4;
        g_Hcl[(size_t)(r0 + r) * 64 + c] = relu_(a1[i] + bb1) + relu_(a2[i] + bb2);
        g_Hue[(size_t)(r0 + r) * 64 + c] = relu_(a3[i] + bb3);
    }
}

// ---------------- layer 3: H_cl + column-sum partials (X updates of l=3 are dead) ----------------
__global__ void __launch_bounds__(256) h_pool_kernel(const float* __restrict__ w1,
                                                     const float* __restrict__ b1,
                                                     const float* __restrict__ w2,
                                                     const float* __restrict__ b2) {
    __shared__ float xs1[16][64], xs2[16][64];
    __shared__ float red[4][64];
    const int tid = threadIdx.x;
    const int r0  = blockIdx.x * 16;
    #pragma unroll
    for (int i = 0; i < 4; ++i) {
        int idx = tid + i * 256;
        int r = idx >> 6, k = idx & 63;
        xs1[r][k] = g_Xc1[(size_t)(r0 + r) * 64 + k];
        xs2[r][k] = g_Xc2[(size_t)(r0 + r) * 64 + k];
    }
    __syncthreads();
    const int c  = tid & 63;
    const int rg = tid >> 6;
    float a1[4] = {0, 0, 0, 0}, a2[4] = {0, 0, 0, 0};
    #pragma unroll 8
    for (int k = 0; k < 64; ++k) {
        float w1k = w1[k * 64 + c], w2k = w2[k * 64 + c];
        #pragma unroll
        for (int i = 0; i < 4; ++i) {
            int r = rg + i * 4;
            a1[i] = fmaf(xs1[r][k], w1k, a1[i]);
            a2[i] = fmaf(xs2[r][k], w2k, a2[i]);
        }
    }
    float bb1 = b1[c], bb2 = b2[c];
    float s = 0.0f;
    #pragma unroll
    for (int i = 0; i < 4; ++i) s += relu_(a1[i] + bb1) + relu_(a2[i] + bb2);
    red[rg][c] = s;
    __syncthreads();
    if (tid < 64)
        g_part[blockIdx.x * 64 + tid] = red[0][tid] + red[1][tid] + red[2][tid] + red[3][tid];
}

// ---------------- final: reduce partials + 2-layer MLP -> out[0] ----------------
__global__ void final_kernel(const float* __restrict__ Qw1, const float* __restrict__ Qb1,
                             const float* __restrict__ Qw2, const float* __restrict__ Qb2,
                             float* __restrict__ out) {
    __shared__ float red[4][64];
    __shared__ float pooled[64];
    __shared__ float z[64];
    int tid = threadIdx.x;
    int c = tid & 63, g = tid >> 6;
    float s = 0.0f;
    for (int p = g; p < 512; p += 4) s += g_part[p * 64 + c];
    red[g][c] = s;
    __syncthreads();
    if (tid < 64) pooled[tid] = red[0][tid] + red[1][tid] + red[2][tid] + red[3][tid];
    __syncthreads();
    if (tid < 64) {
        float a = Qb1[tid];
        #pragma unroll 8
        for (int i = 0; i < 64; ++i) a = fmaf(pooled[i], Qw1[i * 64 + tid], a);
        z[tid] = relu_(a);
    }
    __syncthreads();
    if (tid == 0) {
        float s2 = Qb2[0];
        for (int j = 0; j < 64; ++j) s2 = fmaf(z[j], Qw2[j], s2);
        out[0] = s2;
    }
}

// ---------------- launch ----------------
extern "C" void kernel_launch(void* const* d_in, const int* in_sizes, int n_in,
                              void* d_out, int out_size) {
    (void)in_sizes; (void)n_in; (void)out_size;
    const float* X1   = (const float*)d_in[0];
    const float* X2   = (const float*)d_in[1];
    const float* XU   = (const float*)d_in[2];
    const float* Acl  = (const float*)d_in[3];
    const float* Aue  = (const float*)d_in[4];
    const float* W1w0 = (const float*)d_in[5];
    const float* W1b0 = (const float*)d_in[6];
    const float* W1w  = (const float*)d_in[7];
    const float* W1b  = (const float*)d_in[8];
    const float* W2w0 = (const float*)d_in[9];
    const float* W2b0 = (const float*)d_in[10];
    const float* W2w  = (const float*)d_in[11];
    const float* W2b  = (const float*)d_in[12];
    const float* W3w0 = (const float*)d_in[13];
    const float* W3b0 = (const float*)d_in[14];
    const float* W3w  = (const float*)d_in[15];
    const float* W3b  = (const float*)d_in[16];
    const float* Qw1  = (const float*)d_in[17];
    const float* Qb1  = (const float*)d_in[18];
    const float* Qw2  = (const float*)d_in[19];
    const float* Qb2  = (const float*)d_in[20];
    float* out = (float*)d_out;

    const int smem1 = (2 * 64 * 36 + 2 * 32 * (64 + 8)) * 4;    // 36864 B
    const int smem2 = (2 * 64 * 36 + 2 * 32 * (128 + 8)) * 4;   // 53248 B
    cudaFuncSetAttribute(gemm_kernel<1>, cudaFuncAttributeMaxDynamicSharedMemorySize, smem1);
    cudaFuncSetAttribute(gemm_kernel<2>, cudaFuncAttributeMaxDynamicSharedMemorySize, smem2);

    // layer 0
    h_layer0_kernel<<<2048, 256>>>(X1, X2, XU, W1w0, W1b0, W2w0, W2b0, W3w0, W3b0);
    gemm_kernel<1><<<128, 256, smem1>>>(Acl);   // X_cl_1 = A_cl @ H_cl
    gemm_kernel<2><<<128, 256, smem2>>>(Aue);   // [X_cl_2 | X_ue] = A_ue @ [H_ue | H_cl]

    // layers 1..2
    for (int l = 1; l <= 2; ++l) {
        h_layer_kernel<<<512, 256>>>(W1w + (l - 1) * 4096, W1b + (l - 1) * 64,
                                     W2w + (l - 1) * 4096, W2b + (l - 1) * 64,
                                     W3w + (l - 1) * 4096, W3b + (l - 1) * 64);
        gemm_kernel<1><<<128, 256, smem1>>>(Acl);
        gemm_kernel<2><<<128, 256, smem2>>>(Aue);
    }

    // layer 3: H_cl only + pooling partials, then final MLP
    h_pool_kernel<<<512, 256>>>(W1w + 2 * 4096, W1b + 2 * 64, W2w + 2 * 4096, W2b + 2 * 64);
    final_kernel<<<1, 256>>>(Qw1, Qb1, Qw2, Qb2, out);
}

// round 5
// speedup vs baseline: 1.7111x; 1.7111x over previous
#include <cuda_runtime.h>
#include <cuda_bf16.h>
#include <cstdint>
#include <cstddef>

#define N_NODES 8192
#define DHID 64

// ---------------- scratch (device globals; no allocation allowed) ----------------
__device__ __align__(16) __nv_bfloat16 g_HclT[DHID * N_NODES];  // H_cl^T bf16 [64][8192]
__device__ __align__(16) __nv_bfloat16 g_HueT[DHID * N_NODES];  // H_ue^T bf16 [64][8192]
__device__ __align__(16) float g_Xc1[N_NODES * DHID];
__device__ __align__(16) float g_Xc2[N_NODES * DHID];
__device__ __align__(16) float g_Xue[N_NODES * DHID];
__device__ __align__(16) float g_part[512 * DHID];

__device__ __forceinline__ float relu_(float x) { return fmaxf(x, 0.0f); }

__device__ __forceinline__ uint32_t smem_u32(const void* p) {
    uint32_t a;
    asm("{ .reg .u64 t; cvta.to.shared.u64 t, %1; cvt.u32.u64 %0, t; }" : "=r"(a) : "l"(p));
    return a;
}

__device__ __forceinline__ void ldsm_x4(uint32_t* r, uint32_t addr) {
    asm volatile("ldmatrix.sync.aligned.m8n8.x4.shared.b16 {%0,%1,%2,%3}, [%4];"
                 : "=r"(r[0]), "=r"(r[1]), "=r"(r[2]), "=r"(r[3]) : "r"(addr));
}

__device__ __forceinline__ void mma_bf16(float* c, const uint32_t* a, const uint32_t* b) {
    asm volatile(
        "mma.sync.aligned.m16n8k16.row.col.f32.bf16.bf16.f32 "
        "{%0,%1,%2,%3}, {%4,%5,%6,%7}, {%8,%9}, {%0,%1,%2,%3};"
        : "+f"(c[0]), "+f"(c[1]), "+f"(c[2]), "+f"(c[3])
        : "r"(a[0]), "r"(a[1]), "r"(a[2]), "r"(a[3]), "r"(b[0]), "r"(b[1]));
}

// ---------------- GEMM body: C[8192, ND] = A(fp32) @ Ht^T (Ht bf16 [n][k]) ----------------
// NT=1: ND=64,  C0 = g_Xc1 (Bt0 = HclT)
// NT=2: ND=128, cols 0-63 -> C0 = g_Xc2 (Bt0 = HueT), cols 64-127 -> C1 = g_Xue (Bt1 = HclT)
template <int NT>
__device__ __forceinline__ void gemm_body(const float* __restrict__ A,
                                          const __nv_bfloat16* __restrict__ Bt0,
                                          const __nv_bfloat16* __restrict__ Bt1,
                                          float* __restrict__ C0, float* __restrict__ C1,
                                          int m0, char* smem_raw) {
    constexpr int ND    = 64 * NT;
    constexpr int KC    = 32;                // k per chunk (bf16 elems)
    constexpr int NCH   = N_NODES / KC;      // 256 chunks
    constexpr int ASTRB = 80;                // bytes per smem row (64B data + 16B pad)
    constexpr int ABUF  = 128 * ASTRB;       // 10240 B
    constexpr int BBUF  = ND * ASTRB;        // 5120 * NT
    constexpr int NP    = ND / 32;           // B ldmatrix-x4 pairs per warp (warp n-width = ND/2)

    const int tid  = threadIdx.x;
    const int lane = tid & 31;
    const int wid  = tid >> 5;
    const int wm   = wid & 3;                // 4 M-warps x 32 rows
    const int wn   = wid >> 2;               // 2 N-warps x ND/2 cols

    const uint32_t sb = smem_u32(smem_raw);
    const uint32_t abase[2] = {sb, sb + ABUF};
    const uint32_t bbase[2] = {sb + 2 * ABUF, sb + 2 * ABUF + (uint32_t)BBUF};

    // ---- global A: 128 rows x 128B per chunk; 2 threads/row, 16 floats each ----
    const int arow = tid >> 1;
    const int aseg = tid & 1;
    const float* gA = A + (size_t)(m0 + arow) * N_NODES + aseg * 16;
    const uint32_t asts = (uint32_t)(arow * ASTRB + aseg * 32);

    // ---- global B: ND rows x 64B per chunk; slots of 16B ----
    const __nv_bfloat16* gB[NT];
    uint32_t bsts[NT];
    #pragma unroll
    for (int j = 0; j < NT; ++j) {
        int idx = tid + j * 256;             // over ND*4 slots
        int row = idx >> 2, seg = idx & 3;
        const __nv_bfloat16* base = (NT == 2 && row >= 64)
            ? (Bt1 + (size_t)(row - 64) * N_NODES) : (Bt0 + (size_t)row * N_NODES);
        gB[j]   = base + seg * 8;
        bsts[j] = (uint32_t)(row * ASTRB + seg * 16);
    }

    // ---- ldmatrix lane offsets ----
    uint32_t aoffL[2][2];
    #pragma unroll
    for (int mt = 0; mt < 2; ++mt)
        #pragma unroll
        for (int ks = 0; ks < 2; ++ks)
            aoffL[mt][ks] = (uint32_t)((wm * 32 + mt * 16 + (lane & 15)) * ASTRB +
                                       (ks * 16 + (lane >> 4) * 8) * 2);
    uint32_t boffL[NP][2];
    #pragma unroll
    for (int np = 0; np < NP; ++np)
        #pragma unroll
        for (int ks = 0; ks < 2; ++ks)
            boffL[np][ks] = (uint32_t)((wn * (ND / 2) + np * 16 + (lane >> 4) * 8 + (lane & 7)) * ASTRB +
                                       (ks * 16 + ((lane >> 3) & 1) * 8) * 2);

    float4 ra[4];
    uint4  rbv[NT];

    auto GLOAD = [&](int kt) {
        const float* p = gA + (size_t)kt * KC;
        #pragma unroll
        for (int j = 0; j < 4; ++j) ra[j] = *(const float4*)(p + j * 4);
        #pragma unroll
        for (int j = 0; j < NT; ++j) rbv[j] = *(const uint4*)(gB[j] + (size_t)kt * KC);
    };
    auto STS = [&](int buf) {
        uint32_t r[8];
        #pragma unroll
        for (int j = 0; j < 4; ++j) {
            __nv_bfloat162 lo = __float22bfloat162_rn(make_float2(ra[j].x, ra[j].y));
            __nv_bfloat162 hi = __float22bfloat162_rn(make_float2(ra[j].z, ra[j].w));
            r[j * 2]     = *(uint32_t*)&lo;
            r[j * 2 + 1] = *(uint32_t*)&hi;
        }
        uint32_t ab = abase[buf] + asts;
        asm volatile("st.shared.v4.b32 [%0], {%1,%2,%3,%4};"
                     :: "r"(ab), "r"(r[0]), "r"(r[1]), "r"(r[2]), "r"(r[3]) : "memory");
        asm volatile("st.shared.v4.b32 [%0], {%1,%2,%3,%4};"
                     :: "r"(ab + 16), "r"(r[4]), "r"(r[5]), "r"(r[6]), "r"(r[7]) : "memory");
        #pragma unroll
        for (int j = 0; j < NT; ++j)
            asm volatile("st.shared.v4.b32 [%0], {%1,%2,%3,%4};"
                         :: "r"(bbase[buf] + bsts[j]), "r"(rbv[j].x), "r"(rbv[j].y),
                            "r"(rbv[j].z), "r"(rbv[j].w) : "memory");
    };

    float acc[2][2 * NP][4];
    #pragma unroll
    for (int mt = 0; mt < 2; ++mt)
        #pragma unroll
        for (int nt = 0; nt < 2 * NP; ++nt)
            #pragma unroll
            for (int i = 0; i < 4; ++i) acc[mt][nt][i] = 0.0f;

    GLOAD(0);
    STS(0);
    __syncthreads();

    for (int kt = 0; kt < NCH; ++kt) {
        const int buf = kt & 1;
        if (kt + 1 < NCH) GLOAD(kt + 1);
        #pragma unroll
        for (int ks = 0; ks < 2; ++ks) {
            uint32_t af[2][4], bf[2 * NP][2];
            ldsm_x4(af[0], abase[buf] + aoffL[0][ks]);
            ldsm_x4(af[1], abase[buf] + aoffL[1][ks]);
            #pragma unroll
            for (int np = 0; np < NP; ++np) {
                uint32_t t[4];
                ldsm_x4(t, bbase[buf] + boffL[np][ks]);
                bf[np * 2][0] = t[0]; bf[np * 2][1] = t[1];
                bf[np * 2 + 1][0] = t[2]; bf[np * 2 + 1][1] = t[3];
            }
            #pragma unroll
            for (int mt = 0; mt < 2; ++mt)
                #pragma unroll
                for (int nt = 0; nt < 2 * NP; ++nt)
                    mma_bf16(acc[mt][nt], af[mt], bf[nt]);
        }
        if (kt + 1 < NCH) STS(buf ^ 1);
        __syncthreads();
    }

    // ---- epilogue ----
    const int g = lane >> 2, tig = lane & 3;
    #pragma unroll
    for (int mt = 0; mt < 2; ++mt) {
        int row = m0 + wm * 32 + mt * 16 + g;
        #pragma unroll
        for (int nt = 0; nt < 2 * NP; ++nt) {
            int col = wn * (ND / 2) + nt * 8 + tig * 2;
            float* Cg = C0;
            int cc = col;
            if (NT == 2 && col >= 64) { Cg = C1; cc = col - 64; }
            *(float2*)(Cg + (size_t)row * 64 + cc)       = make_float2(acc[mt][nt][0], acc[mt][nt][1]);
            *(float2*)(Cg + (size_t)(row + 8) * 64 + cc) = make_float2(acc[mt][nt][2], acc[mt][nt][3]);
        }
    }
}

__global__ void __launch_bounds__(256)
gnn_gemm_kernel(const float* __restrict__ Acl, const float* __restrict__ Aue) {
    __shared__ __align__(128) char smem[40960];  // 2*ABUF + 2*BBUF(NT=2)
    const int b = blockIdx.x;
    if (b < 64) gemm_body<1>(Acl, g_HclT, nullptr, g_Xc1, nullptr, b * 128, smem);
    else        gemm_body<2>(Aue, g_HueT, g_HclT, g_Xc2, g_Xue, (b - 64) * 128, smem);
}

// ---------------- layer 0 H (in_dim = 2), writes H^T bf16 ----------------
__global__ void h0_kernel(const float* __restrict__ X1, const float* __restrict__ X2,
                          const float* __restrict__ XU,
                          const float* __restrict__ w1, const float* __restrict__ b1,
                          const float* __restrict__ w2, const float* __restrict__ b2,
                          const float* __restrict__ w3, const float* __restrict__ b3) {
    const int r = blockIdx.x * 256 + threadIdx.x;
    const float2 x1 = *(const float2*)(X1 + r * 2);
    const float2 x2 = *(const float2*)(X2 + r * 2);
    const float2 xu = *(const float2*)(XU + r * 2);
    #pragma unroll 8
    for (int c = 0; c < 64; ++c) {
        float h1 = relu_(fmaf(x1.x, __ldg(w1 + c), fmaf(x1.y, __ldg(w1 + 64 + c), __ldg(b1 + c))));
        float h2 = relu_(fmaf(x2.x, __ldg(w2 + c), fmaf(x2.y, __ldg(w2 + 64 + c), __ldg(b2 + c))));
        float h3 = relu_(fmaf(xu.x, __ldg(w3 + c), fmaf(xu.y, __ldg(w3 + 64 + c), __ldg(b3 + c))));
        g_HclT[c * N_NODES + r] = __float2bfloat16(h1 + h2);
        g_HueT[c * N_NODES + r] = __float2bfloat16(h3);
    }
}

// ---------------- layers 1..2 H (in_dim = 64), writes H^T bf16 ----------------
__global__ void __launch_bounds__(256) h_layer_kernel(const float* __restrict__ w1,
                                                      const float* __restrict__ b1,
                                                      const float* __restrict__ w2,
                                                      const float* __restrict__ b2,
                                                      const float* __restrict__ w3,
                                                      const float* __restrict__ b3) {
    __shared__ float xs1[16][64], xs2[16][64], xs3[16][64];
    __shared__ __align__(16) __nv_bfloat16 hs_cl[64][16];
    __shared__ __align__(16) __nv_bfloat16 hs_ue[64][16];
    const int tid = threadIdx.x;
    const int r0  = blockIdx.x * 16;
    #pragma unroll
    for (int i = 0; i < 4; ++i) {
        int idx = tid + i * 256;
        int r = idx >> 6, k = idx & 63;
        xs1[r][k] = g_Xc1[(size_t)(r0 + r) * 64 + k];
        xs2[r][k] = g_Xc2[(size_t)(r0 + r) * 64 + k];
        xs3[r][k] = g_Xue[(size_t)(r0 + r) * 64 + k];
    }
    __syncthreads();
    const int c  = tid & 63;
    const int rg = tid >> 6;
    float a1[4] = {0, 0, 0, 0}, a2[4] = {0, 0, 0, 0}, a3[4] = {0, 0, 0, 0};
    #pragma unroll 8
    for (int k = 0; k < 64; ++k) {
        float w1k = w1[k * 64 + c], w2k = w2[k * 64 + c], w3k = w3[k * 64 + c];
        #pragma unroll
        for (int i = 0; i < 4; ++i) {
            int r = rg + i * 4;
            a1[i] = fmaf(xs1[r][k], w1k, a1[i]);
            a2[i] = fmaf(xs2[r][k], w2k, a2[i]);
            a3[i] = fmaf(xs3[r][k], w3k, a3[i]);
        }
    }
    const float bb1 = b1[c], bb2 = b2[c], bb3 = b3[c];
    #pragma unroll
    for (int i = 0; i < 4; ++i) {
        int r = rg + i * 4;
        hs_cl[c][r] = __float2bfloat16(relu_(a1[i] + bb1) + relu_(a2[i] + bb2));
        hs_ue[c][r] = __float2bfloat16(relu_(a3[i] + bb3));
    }
    __syncthreads();
    if (tid < 128) {
        int cc = tid >> 1, hf = tid & 1;
        *(uint4*)(g_HclT + cc * N_NODES + r0 + hf * 8) = *(const uint4*)(&hs_cl[cc][hf * 8]);
    } else {
        int t = tid - 128;
        int cc = t >> 1, hf = t & 1;
        *(uint4*)(g_HueT + cc * N_NODES + r0 + hf * 8) = *(const uint4*)(&hs_ue[cc][hf * 8]);
    }
}

// ---------------- layer 3: H_cl + column-sum partials (X updates are dead) ----------------
__global__ void __launch_bounds__(256) h_pool_kernel(const float* __restrict__ w1,
                                                     const float* __restrict__ b1,
                                                     const float* __restrict__ w2,
                                                     const float* __restrict__ b2) {
    __shared__ float xs1[16][64], xs2[16][64];
    __shared__ float red[4][64];
    const int tid = threadIdx.x;
    const int r0  = blockIdx.x * 16;
    #pragma unroll
    for (int i = 0; i < 4; ++i) {
        int idx = tid + i * 256;
        int r = idx >> 6, k = idx & 63;
        xs1[r][k] = g_Xc1[(size_t)(r0 + r) * 64 + k];
        xs2[r][k] = g_Xc2[(size_t)(r0 + r) * 64 + k];
    }
    __syncthreads();
    const int c  = tid & 63;
    const int rg = tid >> 6;
    float a1[4] = {0, 0, 0, 0}, a2[4] = {0, 0, 0, 0};
    #pragma unroll 8
    for (int k = 0; k < 64; ++k) {
        float w1k = w1[k * 64 + c], w2k = w2[k * 64 + c];
        #pragma unroll
        for (int i = 0; i < 4; ++i) {
            int r = rg + i * 4;
            a1[i] = fmaf(xs1[r][k], w1k, a1[i]);
            a2[i] = fmaf(xs2[r][k], w2k, a2[i]);
        }
    }
    const float bb1 = b1[c], bb2 = b2[c];
    float s = 0.0f;
    #pragma unroll
    for (int i = 0; i < 4; ++i) s += relu_(a1[i] + bb1) + relu_(a2[i] + bb2);
    red[rg][c] = s;
    __syncthreads();
    if (tid < 64)
        g_part[blockIdx.x * 64 + tid] = red[0][tid] + red[1][tid] + red[2][tid] + red[3][tid];
}

// ---------------- final: reduce partials + 2-layer MLP -> out[0] ----------------
__global__ void final_kernel(const float* __restrict__ Qw1, const float* __restrict__ Qb1,
                             const float* __restrict__ Qw2, const float* __restrict__ Qb2,
                             float* __restrict__ out) {
    __shared__ float red[4][64];
    __shared__ float pooled[64];
    __shared__ float z[64];
    int tid = threadIdx.x;
    int c = tid & 63, g = tid >> 6;
    float s = 0.0f;
    for (int p = g; p < 512; p += 4) s += g_part[p * 64 + c];
    red[g][c] = s;
    __syncthreads();
    if (tid < 64) pooled[tid] = red[0][tid] + red[1][tid] + red[2][tid] + red[3][tid];
    __syncthreads();
    if (tid < 64) {
        float a = Qb1[tid];
        #pragma unroll 8
        for (int i = 0; i < 64; ++i) a = fmaf(pooled[i], Qw1[i * 64 + tid], a);
        z[tid] = relu_(a);
    }
    __syncthreads();
    if (tid == 0) {
        float s2 = Qb2[0];
        for (int j = 0; j < 64; ++j) s2 = fmaf(z[j], Qw2[j], s2);
        out[0] = s2;
    }
}

// ---------------- launch ----------------
extern "C" void kernel_launch(void* const* d_in, const int* in_sizes, int n_in,
                              void* d_out, int out_size) {
    (void)in_sizes; (void)n_in; (void)out_size;
    const float* X1   = (const float*)d_in[0];
    const float* X2   = (const float*)d_in[1];
    const float* XU   = (const float*)d_in[2];
    const float* Acl  = (const float*)d_in[3];
    const float* Aue  = (const float*)d_in[4];
    const float* W1w0 = (const float*)d_in[5];
    const float* W1b0 = (const float*)d_in[6];
    const float* W1w  = (const float*)d_in[7];
    const float* W1b  = (const float*)d_in[8];
    const float* W2w0 = (const float*)d_in[9];
    const float* W2b0 = (const float*)d_in[10];
    const float* W2w  = (const float*)d_in[11];
    const float* W2b  = (const float*)d_in[12];
    const float* W3w0 = (const float*)d_in[13];
    const float* W3b0 = (const float*)d_in[14];
    const float* W3w  = (const float*)d_in[15];
    const float* W3b  = (const float*)d_in[16];
    const float* Qw1  = (const float*)d_in[17];
    const float* Qb1  = (const float*)d_in[18];
    const float* Qw2  = (const float*)d_in[19];
    const float* Qb2  = (const float*)d_in[20];
    float* out = (float*)d_out;

    // layer 0
    h0_kernel<<<32, 256>>>(X1, X2, XU, W1w0, W1b0, W2w0, W2b0, W3w0, W3b0);
    gnn_gemm_kernel<<<128, 256>>>(Acl, Aue);

    // layers 1..2
    for (int l = 1; l <= 2; ++l) {
        h_layer_kernel<<<512, 256>>>(W1w + (l - 1) * 4096, W1b + (l - 1) * 64,
                                     W2w + (l - 1) * 4096, W2b + (l - 1) * 64,
                                     W3w + (l - 1) * 4096, W3b + (l - 1) * 64);
        gnn_gemm_kernel<<<128, 256>>>(Acl, Aue);
    }

    // layer 3: H_cl only + pooling partials, then final MLP
    h_pool_kernel<<<512, 256>>>(W1w + 2 * 4096, W1b + 2 * 64, W2w + 2 * 4096, W2b + 2 * 64);
    final_kernel<<<1, 256>>>(Qw1, Qb1, Qw2, Qb2, out);
}